// round 2
// baseline (speedup 1.0000x reference)
#include <cuda_runtime.h>
#include <cuda_bf16.h>

// TimeWarp: out[b,i,j] = bilerp over S[b, y(j), x(i)]
//   x_pix(i) = (i/127)*8191           (freq index -> time coordinate, swapped-grid quirk)
//   idx(j)   = j < dest ? j*src/dest : src + (j-dest)*(8192-src)/(8192-dest)
//   y_pix(j) = clip(idx,0,8191)/8191*127
// B=32, F=128, T=8192, fp32.

#define NB 32
#define NF 128
#define NT 8192

__global__ __launch_bounds__(256, 8)
void timewarp_kernel(const float* __restrict__ S,
                     const int*   __restrict__ psrc,
                     const int*   __restrict__ pdst,
                     float*       __restrict__ out)
{
    const int tid = blockIdx.x * blockDim.x + threadIdx.x;
    // 2048 float4-chunks per (b,i) row; consecutive lanes -> consecutive j (coalesced STG.128)
    const int j0 = (tid & 2047) << 2;          // 0..8188 step 4
    const int i  = (tid >> 11) & (NF - 1);     // 0..127
    const int b  = tid >> 18;                  // 0..31   (2048*128 = 2^18)

    const float s = (float)__ldg(psrc);
    const float d = (float)__ldg(pdst);
    // idx = t/left_ratio = t*(s/d) for t<d ; idx = s + (t-d)*(NT-s)/(NT-d) otherwise
    const float rl = s / d;
    const float rr = ((float)NT - s) / ((float)NT - d);

    // ---- x side (depends only on i) ----
    float x_pix = ((float)i / 127.0f) * 8191.0f;
    x_pix = fminf(fmaxf(x_pix, 0.0f), 8191.0f);
    const float x0f = floorf(x_pix);
    const int   x0  = (int)x0f;
    const int   x1  = min(x0 + 1, NT - 1);
    const float wx  = x_pix - x0f;

    // ---- y side: 4 consecutive j ----
    float yp[4];
#pragma unroll
    for (int k = 0; k < 4; k++) {
        float t   = (float)(j0 + k);
        float idx = (t < d) ? (t * rl) : fmaf(t - d, rr, s);
        idx = fminf(fmaxf(idx, 0.0f), 8191.0f);
        float y = idx * (1.0f / 8191.0f) * 127.0f;
        yp[k] = fminf(fmaxf(y, 0.0f), 127.0f);
    }

    // y_pix is monotone, slope ~0.0155/j -> floor spans <=2 values over 4 j's.
    // Load 3 candidate rows (clamped), lerp along x once per row, select per j.
    const float Yf = floorf(yp[0]);
    const int   Y  = (int)Yf;
    const int   rB = min(Y + 1, NF - 1);
    const int   rC = min(Y + 2, NF - 1);

    const float* Sb = S + (size_t)b * (size_t)(NF * NT);
    const float a0 = __ldg(Sb + (size_t)Y  * NT + x0);
    const float a1 = __ldg(Sb + (size_t)Y  * NT + x1);
    const float b0 = __ldg(Sb + (size_t)rB * NT + x0);
    const float b1 = __ldg(Sb + (size_t)rB * NT + x1);
    const float c0 = __ldg(Sb + (size_t)rC * NT + x0);
    const float c1 = __ldg(Sb + (size_t)rC * NT + x1);

    const float rowA = fmaf(wx, a1 - a0, a0);  // row Y   resampled at x_pix
    const float rowB = fmaf(wx, b1 - b0, b0);  // row Y+1
    const float rowC = fmaf(wx, c1 - c0, c0);  // row Y+2

    float o[4];
#pragma unroll
    for (int k = 0; k < 4; k++) {
        float yf = floorf(yp[k]);
        float wy = yp[k] - yf;
        bool  up = (yf > Yf);                 // floor advanced by exactly 1
        float lo = up ? rowB : rowA;
        float hi = up ? rowC : rowB;
        o[k] = fmaf(wy, hi - lo, lo);         // (1-wy)*lo + wy*hi
    }

    const size_t off = ((size_t)b * NF + i) * (size_t)NT + (size_t)j0;
    float4 res = make_float4(o[0], o[1], o[2], o[3]);
    *reinterpret_cast<float4*>(out + off) = res;
}

extern "C" void kernel_launch(void* const* d_in, const int* in_sizes, int n_in,
                              void* d_out, int out_size)
{
    const float* S    = (const float*)d_in[0];
    const int*   psrc = (const int*)d_in[1];
    const int*   pdst = (const int*)d_in[2];
    float*       out  = (float*)d_out;

    // total threads = 32 * 128 * 2048 = 8388608 -> 32768 blocks of 256
    const int threads = 256;
    const int blocks  = (NB * NF * (NT / 4)) / threads;
    timewarp_kernel<<<blocks, threads>>>(S, psrc, pdst, out);
}

// round 3
// speedup vs baseline: 1.0985x; 1.0985x over previous
#include <cuda_runtime.h>
#include <cuda_bf16.h>

// TimeWarp, two-phase:
//  Phase 1 (prep): P[b,r,i] = lerp_x(S[b,r,:], x_pix(i))   -- 32 x 132 x 128 (rows 128..131 pad = row 127)
//                  wy[j], rowofs[chunk]=floor(y(j0))*128
//  Phase 2 (hot):  out[b,i,j] = lerp_y(P[b,:,i], y(j))  -- pure streaming store
// B=32, F=128, T=8192, fp32.

#define NB 32
#define NF 128
#define NT 8192
#define PR 132                    // padded rows per batch (128 real + 4 dup of row 127)

__device__ __align__(16) float g_P[NB * PR * NF];   // ~2.2 MB, L2-resident
__device__ __align__(16) float g_wy[NT];
__device__ __align__(16) int   g_rowofs[NT / 4];

// ---------------- Phase 1: resample along x, build tables ----------------
__global__ __launch_bounds__(256)
void prep_kernel(const float* __restrict__ S,
                 const int* __restrict__ psrc,
                 const int* __restrict__ pdst)
{
    const int tid = blockIdx.x * blockDim.x + threadIdx.x;

    // ---- per-j warp tables (first 8192 threads) ----
    if (tid < NT) {
        const float s = (float)__ldg(psrc);
        const float d = (float)__ldg(pdst);
        const float rl = s / d;
        const float rr = ((float)NT - s) / ((float)NT - d);
        float t = (float)tid;
        float idx = (t < d) ? (t * rl) : fmaf(t - d, rr, s);
        idx = fminf(fmaxf(idx, 0.0f), (float)(NT - 1));
        float y = idx * (1.0f / (float)(NT - 1)) * (float)(NF - 1);
        y = fminf(fmaxf(y, 0.0f), (float)(NF - 1));
        float yf = floorf(y);
        g_wy[tid] = y - yf;
        if ((tid & 3) == 0) g_rowofs[tid >> 2] = (int)yf * NF;
    }

    // ---- P tensor: tid = b*(PR*NF) + r*NF + i ----
    if (tid < NB * PR * NF) {
        const int i = tid & (NF - 1);
        const int r = (tid >> 7) % PR;
        const int b = tid / (PR * NF);
        const int rs = min(r, NF - 1);           // pad rows duplicate row 127

        float x_pix = ((float)i / (float)(NF - 1)) * (float)(NT - 1);
        x_pix = fminf(fmaxf(x_pix, 0.0f), (float)(NT - 1));
        const float x0f = floorf(x_pix);
        const int   x0  = (int)x0f;
        const int   x1  = min(x0 + 1, NT - 1);
        const float wx  = x_pix - x0f;

        const float* row = S + ((size_t)b * NF + rs) * (size_t)NT;
        const float v0 = __ldg(row + x0);
        const float v1 = __ldg(row + x1);
        g_P[tid] = fmaf(wx, v1 - v0, v0);
    }
}

// ---------------- Phase 2: streaming y-lerp ----------------
__global__ __launch_bounds__(256, 8)
void warp_kernel(float* __restrict__ out)
{
    const int tid   = blockIdx.x * blockDim.x + threadIdx.x;
    const int chunk = tid & (NT / 4 - 1);        // consecutive lanes -> consecutive chunks
    const int i     = (tid >> 11) & (NF - 1);
    const int b     = tid >> 18;

    const float4 wy  = reinterpret_cast<const float4*>(g_wy)[chunk];   // coalesced 512B/warp
    const int    ofs = g_rowofs[chunk];                                // floor(y(j0)) * 128

    const float* p = g_P + (b * (PR * NF) + i) + ofs;
    const float pA = p[0];            // row Y    (resampled at x_pix(i))
    const float pB = p[NF];           // row Y+1
    const float pC = p[2 * NF];       // row Y+2  (pad-safe)

    // floor(y) advances within the chunk exactly where the fractional part wraps:
    // sel_k = (wy_k < wy_0)   (y-span over 4 j's << 1)
    float o0 = fmaf(wy.x, pB - pA, pA);
    bool s1 = wy.y < wy.x;  float l1 = s1 ? pB : pA, h1 = s1 ? pC : pB;
    bool s2 = wy.z < wy.x;  float l2 = s2 ? pB : pA, h2 = s2 ? pC : pB;
    bool s3 = wy.w < wy.x;  float l3 = s3 ? pB : pA, h3 = s3 ? pC : pB;
    float o1 = fmaf(wy.y, h1 - l1, l1);
    float o2 = fmaf(wy.z, h2 - l2, l2);
    float o3 = fmaf(wy.w, h3 - l3, l3);

    const size_t off = ((size_t)b * NF + i) * (size_t)NT + ((size_t)chunk << 2);
    *reinterpret_cast<float4*>(out + off) = make_float4(o0, o1, o2, o3);
}

extern "C" void kernel_launch(void* const* d_in, const int* in_sizes, int n_in,
                              void* d_out, int out_size)
{
    const float* S    = (const float*)d_in[0];
    const int*   psrc = (const int*)d_in[1];
    const int*   pdst = (const int*)d_in[2];
    float*       out  = (float*)d_out;

    // Phase 1: 32*132*128 = 540672 threads = 2112 blocks of 256
    prep_kernel<<<(NB * PR * NF + 255) / 256, 256>>>(S, psrc, pdst);

    // Phase 2: 32*128*2048 = 8388608 threads = 32768 blocks of 256
    warp_kernel<<<(NB * NF * (NT / 4)) / 256, 256>>>(out);
}

// round 4
// speedup vs baseline: 1.4422x; 1.3128x over previous
#include <cuda_runtime.h>
#include <cuda_bf16.h>

// TimeWarp, single fused kernel.
// Block = (b, j-tile of TILE_J=256 time steps), covering ALL 128 freq rows.
//   Setup:  wy[256], per-chunk Y[64], and the x-resampled P-tile (<=12 rows x 128) in smem.
//   Stream: out[b,i,j] = lerp_y over smem P-tile; coalesced STG.128 with streaming hint.
// B=32, F=128, T=8192, fp32.

#define NB 32
#define NF 128
#define NT 8192
#define TILE_J   256              // j's per block
#define TILE_C   (TILE_J / 4)     // 64 float4-chunks per block
#define MAX_ROWS 12               // y-span over 256 j's <= ~4.1 (+2 lerp/pad +1) -> <=8; 12 is safe

__global__ __launch_bounds__(256, 8)
void timewarp_fused(const float* __restrict__ S,
                    const int*   __restrict__ psrc,
                    const int*   __restrict__ pdst,
                    float*       __restrict__ out)
{
    __shared__ float  sP[MAX_ROWS * NF];     // x-resampled rows [Ymin .. Ymin+nrows)
    __shared__ float4 sWy4[TILE_C];          // frac(y) per j, viewed as float4 per chunk
    __shared__ int    sYc[TILE_C];           // floor(y) at each chunk's first j

    const int t  = threadIdx.x;              // 256 threads
    const int jt = blockIdx.x;               // 0..31  j-tile
    const int b  = blockIdx.y;               // 0..31  batch
    const int j_base = jt * TILE_J;

    // ---------- Phase 1a: per-j tables ----------
    {
        const float s = (float)__ldg(psrc);
        const float d = (float)__ldg(pdst);
        const float rl = s / d;
        const float rr = ((float)NT - s) / ((float)NT - d);

        float tf  = (float)(j_base + t);
        float idx = (tf < d) ? (tf * rl) : fmaf(tf - d, rr, s);
        idx = fminf(fmaxf(idx, 0.0f), (float)(NT - 1));
        float y = idx * (1.0f / (float)(NT - 1)) * (float)(NF - 1);
        y = fminf(fmaxf(y, 0.0f), (float)(NF - 1));
        float yf = floorf(y);
        ((float*)sWy4)[t] = y - yf;
        if ((t & 3) == 0) sYc[t >> 2] = (int)yf;
    }
    __syncthreads();

    // ---------- Phase 1b: build P-tile (x-resample needed rows) ----------
    const int Ymin  = sYc[0];                        // y(j) monotone nondecreasing
    int nrows = sYc[TILE_C - 1] + 2 - Ymin + 1;      // cover Y..Y+2 of last chunk
    if (nrows > MAX_ROWS) nrows = MAX_ROWS;

    const float* Sb = S + (size_t)b * (size_t)(NF * NT);
    for (int v = t; v < nrows * NF; v += 256) {
        const int r  = v >> 7;
        const int i  = v & (NF - 1);
        const int rs = min(Ymin + r, NF - 1);        // border clamp / pad rows

        float x_pix = ((float)i / (float)(NF - 1)) * (float)(NT - 1);
        x_pix = fminf(fmaxf(x_pix, 0.0f), (float)(NT - 1));
        const float x0f = floorf(x_pix);
        const int   x0  = (int)x0f;
        const int   x1  = min(x0 + 1, NT - 1);
        const float wx  = x_pix - x0f;

        const float* row = Sb + (size_t)rs * NT;
        const float v0 = __ldg(row + x0);
        const float v1 = __ldg(row + x1);
        sP[v] = fmaf(wx, v1 - v0, v0);
    }
    __syncthreads();

    // ---------- Phase 2: stream all 128 freq rows ----------
    const int tx = t & (TILE_C - 1);                 // chunk within tile (warp-contiguous)
    const int ty = t >> 6;                           // i-offset 0..3

    const float4 wy = sWy4[tx];
    const int    rel = sYc[tx] - Ymin;               // 0..nrows-3
    const float* pc  = sP + rel * NF;

    const bool s1 = wy.y < wy.x;
    const bool s2 = wy.z < wy.x;
    const bool s3 = wy.w < wy.x;

    float* obase = out + ((size_t)b * NF) * (size_t)NT + (size_t)(j_base + tx * 4);

#pragma unroll 4
    for (int ig = 0; ig < NF / 4; ig++) {
        const int i = ig * 4 + ty;

        const float pA = pc[i];
        const float pB = pc[NF + i];
        const float pC = pc[2 * NF + i];

        float o0 = fmaf(wy.x, pB - pA, pA);
        float l1 = s1 ? pB : pA, h1 = s1 ? pC : pB;
        float l2 = s2 ? pB : pA, h2 = s2 ? pC : pB;
        float l3 = s3 ? pB : pA, h3 = s3 ? pC : pB;
        float o1 = fmaf(wy.y, h1 - l1, l1);
        float o2 = fmaf(wy.z, h2 - l2, l2);
        float o3 = fmaf(wy.w, h3 - l3, l3);

        __stcs(reinterpret_cast<float4*>(obase + (size_t)i * NT),
               make_float4(o0, o1, o2, o3));
    }
}

extern "C" void kernel_launch(void* const* d_in, const int* in_sizes, int n_in,
                              void* d_out, int out_size)
{
    const float* S    = (const float*)d_in[0];
    const int*   psrc = (const int*)d_in[1];
    const int*   pdst = (const int*)d_in[2];
    float*       out  = (float*)d_out;

    dim3 grid(NT / TILE_J, NB);   // 32 x 32 = 1024 blocks
    timewarp_fused<<<grid, 256>>>(S, psrc, pdst, out);
}